// round 12
// baseline (speedup 1.0000x reference)
#include <cuda_runtime.h>
#include <cuda_fp16.h>
#include <cstdint>
#include <cstddef>

#define N_NODES 32768
#define N_EDGES 524288

// ---- scratch (device globals; allocations forbidden) ----
__device__ float  g_x[(size_t)N_NODES * 256];     // [0:64]=x0, [64+u*3+i]=x1[u][i]
__device__ float  g_m[(size_t)N_NODES * 512];     // [0:128]=m0, [128+v*3+i]=m1
__device__ __half g_tpw[(size_t)N_EDGES * 256];   // per-edge radial MLP output (fp16)
__device__ float  g_wt0[64 * 64 * 12];            // W_skip0 as [v][u][w-pad12]
__device__ float  g_wt1[64 * 64 * 12];
__device__ int    g_cnt[N_NODES];                 // histogram
__device__ int    g_cur[N_NODES];                 // scatter cursor
__device__ int    g_rowptr[N_NODES + 1];
__device__ int    g_eid[N_EDGES];

#define C_UP      0.125f
#define C_R1      0.35355339059327373f
#define C_R       0.125f
#define C_LIN     0.00552427172801990f
#define C_SKIP    0.03952847075210474f
#define INV_SQRT3 0.5773502691896258f

__device__ __forceinline__ float silu_f(float x) {
    return __fdividef(x, 1.0f + __expf(-x));
}
__device__ __forceinline__ unsigned int h2_bits(__half2 h) {
    return *reinterpret_cast<unsigned int*>(&h);
}

// ==== K_prep: W_skip (64,64,10)[u,v,w] -> [v][u][12] (w-padded) ====
__global__ void k_prep(const float* __restrict__ Ws0, const float* __restrict__ Ws1) {
    int idx = blockIdx.x * 256 + threadIdx.x;   // 0 .. 49151
    int v = idx / 768;
    int r = idx % 768;
    int u = r / 12, w = r % 12;
    float a = 0.f, b = 0.f;
    if (w < 10) {
        a = Ws0[u * 640 + v * 10 + w];
        b = Ws1[u * 640 + v * 10 + w];
    }
    g_wt0[idx] = a;
    g_wt1[idx] = b;
}

// ==== K0: node up-projection (8 nodes/block) ====
__global__ __launch_bounds__(256) void k_node_up(const float* __restrict__ nf,
                                                 const float* __restrict__ Wu0,
                                                 const float* __restrict__ Wu1) {
    __shared__ float sW0[4096], sW1[4096], sIn[2048];
    const int t = threadIdx.x;
    for (int i = t; i < 4096; i += 256) { sW0[i] = Wu0[i]; sW1[i] = Wu1[i]; }
    const int n0 = blockIdx.x * 8;
    for (int i = t; i < 2048; i += 256) sIn[i] = nf[(size_t)n0 * 256 + i];
    __syncthreads();
    const int j = t >> 6, u = t & 63;
    const int off0 = (j == 0) ? 0 : (63 + j);
    const int st = (j == 0) ? 1 : 3;
    const float* W = (j == 0) ? sW0 : sW1;
    const int oo = (j == 0) ? u : (64 + u * 3 + (j - 1));
    for (int c = 0; c < 2; c++) {
        float acc[4] = {0.f, 0.f, 0.f, 0.f};
        #pragma unroll 8
        for (int v = 0; v < 64; v++) {
            float w = W[v * 64 + u];
            #pragma unroll
            for (int r = 0; r < 4; r++)
                acc[r] += sIn[(c * 4 + r) * 256 + off0 + v * st] * w;
        }
        #pragma unroll
        for (int r = 0; r < 4; r++)
            g_x[(size_t)(n0 + c * 4 + r) * 256 + oo] = acc[r] * C_UP;
    }
}

// ==== CSR build over dst ====
__global__ void k_hist(const int* __restrict__ dst) {
    int e = blockIdx.x * 256 + threadIdx.x;
    atomicAdd(&g_cnt[dst[e]], 1);
}

__global__ __launch_bounds__(1024) void k_scan() {
    __shared__ int part[1024];
    const int t = threadIdx.x;
    int4 c4[8];
    const int4* cp = (const int4*)(g_cnt + t * 32);
    #pragma unroll
    for (int j = 0; j < 8; j++) c4[j] = cp[j];     // 8 independent LDG.128
    int vals[32];
    #pragma unroll
    for (int j = 0; j < 8; j++) {
        vals[j*4+0] = c4[j].x; vals[j*4+1] = c4[j].y;
        vals[j*4+2] = c4[j].z; vals[j*4+3] = c4[j].w;
    }
    int loc[32];
    int s = 0;
    #pragma unroll
    for (int j = 0; j < 32; j++) { loc[j] = s; s += vals[j]; }
    part[t] = s;
    __syncthreads();
    for (int off = 1; off < 1024; off <<= 1) {
        int v = (t >= off) ? part[t - off] : 0;
        __syncthreads();
        part[t] += v;
        __syncthreads();
    }
    int pre = (t == 0) ? 0 : part[t - 1];
    #pragma unroll
    for (int j = 0; j < 32; j++) {
        int o = pre + loc[j];
        g_rowptr[t * 32 + j] = o;
        g_cur[t * 32 + j] = o;
    }
    if (t == 1023) g_rowptr[N_NODES] = part[1023];
}

__global__ void k_scatter(const int* __restrict__ dst) {
    int e = blockIdx.x * 256 + threadIdx.x;
    int p = atomicAdd(&g_cur[dst[e]], 1);
    g_eid[p] = e;
}

// ==== K1: radial MLP only -> g_tpw (fp16). 512 threads, 128 edges/tile ====
#define ST_H 65
#define OFF_WR1 0
#define OFF_WR2 512
#define OFF_WR3 4608
#define OFF_WR4 8704
#define OFF_HA  25088
#define OFF_HB  (OFF_HA + 128*ST_H)       // 33408
#define OFF_EF  (OFF_HB + 128*ST_H)       // 41728
#define K1_SMEM_FLOATS (OFF_EF + 1024)    // 42752 floats -> 171008 B

template<int K, bool SILU>
__device__ __forceinline__ void gemm_t(const float* __restrict__ A, int astride,
                                       const float* __restrict__ B,
                                       float* __restrict__ O,
                                       float scale, int e0, int e1, int cb) {
    float acc[2][8];
    #pragma unroll
    for (int r = 0; r < 2; r++)
        #pragma unroll
        for (int j = 0; j < 8; j++) acc[r][j] = 0.f;
    #pragma unroll 8
    for (int k = 0; k < K; k++) {
        float a0 = A[e0 * astride + k];
        float a1 = A[e1 * astride + k];
        const float4 b0 = *(const float4*)(B + k * 64 + cb);
        const float4 b1 = *(const float4*)(B + k * 64 + cb + 4);
        acc[0][0] += a0*b0.x; acc[0][1] += a0*b0.y; acc[0][2] += a0*b0.z; acc[0][3] += a0*b0.w;
        acc[0][4] += a0*b1.x; acc[0][5] += a0*b1.y; acc[0][6] += a0*b1.z; acc[0][7] += a0*b1.w;
        acc[1][0] += a1*b0.x; acc[1][1] += a1*b0.y; acc[1][2] += a1*b0.z; acc[1][3] += a1*b0.w;
        acc[1][4] += a1*b1.x; acc[1][5] += a1*b1.y; acc[1][6] += a1*b1.z; acc[1][7] += a1*b1.w;
    }
    #pragma unroll
    for (int r = 0; r < 2; r++) {
        const int e = r ? e1 : e0;
        #pragma unroll
        for (int j = 0; j < 8; j++) {
            float x = acc[r][j] * scale;
            O[e * ST_H + cb + j] = SILU ? silu_f(x) : x;
        }
    }
}

// L4: 4 edges x 16 cols per thread (64 acc) -> low LDS pressure, FMA-bound
__device__ __forceinline__ void l4_store(const float* __restrict__ H,
                                         const float* __restrict__ W4,
                                         __half* __restrict__ gout,
                                         int t) {
    const int tg  = t >> 4;          // 0..31 -> edges 4tg..4tg+3
    const int tcc = (t & 15) * 16;   // col base, 0..240
    float acc[4][16];
    #pragma unroll
    for (int i = 0; i < 4; i++)
        #pragma unroll
        for (int j = 0; j < 16; j++) acc[i][j] = 0.f;
    #pragma unroll 4
    for (int k = 0; k < 64; k++) {
        float a[4];
        #pragma unroll
        for (int i = 0; i < 4; i++) a[i] = H[(4*tg + i) * ST_H + k];
        const float* B = W4 + k * 256 + tcc;
        const float4 b0 = *(const float4*)(B);
        const float4 b1 = *(const float4*)(B + 4);
        const float4 b2 = *(const float4*)(B + 8);
        const float4 b3 = *(const float4*)(B + 12);
        #pragma unroll
        for (int i = 0; i < 4; i++) {
            acc[i][0]  += a[i]*b0.x; acc[i][1]  += a[i]*b0.y;
            acc[i][2]  += a[i]*b0.z; acc[i][3]  += a[i]*b0.w;
            acc[i][4]  += a[i]*b1.x; acc[i][5]  += a[i]*b1.y;
            acc[i][6]  += a[i]*b1.z; acc[i][7]  += a[i]*b1.w;
            acc[i][8]  += a[i]*b2.x; acc[i][9]  += a[i]*b2.y;
            acc[i][10] += a[i]*b2.z; acc[i][11] += a[i]*b2.w;
            acc[i][12] += a[i]*b3.x; acc[i][13] += a[i]*b3.y;
            acc[i][14] += a[i]*b3.z; acc[i][15] += a[i]*b3.w;
        }
    }
    #pragma unroll
    for (int i = 0; i < 4; i++) {
        uint4 pk0, pk1;
        __half2 h;
        h = __floats2half2_rn(acc[i][0]*C_R,  acc[i][1]*C_R);  pk0.x = h2_bits(h);
        h = __floats2half2_rn(acc[i][2]*C_R,  acc[i][3]*C_R);  pk0.y = h2_bits(h);
        h = __floats2half2_rn(acc[i][4]*C_R,  acc[i][5]*C_R);  pk0.z = h2_bits(h);
        h = __floats2half2_rn(acc[i][6]*C_R,  acc[i][7]*C_R);  pk0.w = h2_bits(h);
        h = __floats2half2_rn(acc[i][8]*C_R,  acc[i][9]*C_R);  pk1.x = h2_bits(h);
        h = __floats2half2_rn(acc[i][10]*C_R, acc[i][11]*C_R); pk1.y = h2_bits(h);
        h = __floats2half2_rn(acc[i][12]*C_R, acc[i][13]*C_R); pk1.z = h2_bits(h);
        h = __floats2half2_rn(acc[i][14]*C_R, acc[i][15]*C_R); pk1.w = h2_bits(h);
        __half* op = gout + (size_t)(4*tg + i) * 256 + tcc;
        *(uint4*)(op)     = pk0;
        *(uint4*)(op + 8) = pk1;
    }
}

__global__ __launch_bounds__(512, 1) void k_edge_mlp(const float* __restrict__ ef,
                                                     const float* __restrict__ Wr1,
                                                     const float* __restrict__ Wr2,
                                                     const float* __restrict__ Wr3,
                                                     const float* __restrict__ Wr4) {
    extern __shared__ float sm[];
    float* sWr1 = sm + OFF_WR1;
    float* sWr2 = sm + OFF_WR2;
    float* sWr3 = sm + OFF_WR3;
    float* sWr4 = sm + OFF_WR4;
    float* sHa  = sm + OFF_HA;
    float* sHb  = sm + OFF_HB;
    float* sEF  = sm + OFF_EF;
    const int t = threadIdx.x;
    if (t < 512) sWr1[t] = Wr1[t];
    for (int i = t; i < 4096;  i += 512) { sWr2[i] = Wr2[i]; sWr3[i] = Wr3[i]; }
    for (int i = t; i < 16384; i += 512) sWr4[i] = Wr4[i];
    const int te = t >> 3, tc = t & 7;
    const int e0 = te * 2, e1 = te * 2 + 1, cb = tc * 8;

    for (int tile = blockIdx.x; tile < N_EDGES / 128; tile += gridDim.x) {
        const int eg = tile * 128;
        __syncthreads();
        for (int i = t; i < 1024; i += 512) sEF[i] = ef[(size_t)eg * 8 + i];
        __syncthreads();
        gemm_t<8,  true>(sEF, 8,    sWr1, sHa, C_R1, e0, e1, cb);
        __syncthreads();
        gemm_t<64, true>(sHa, ST_H, sWr2, sHb, C_R,  e0, e1, cb);
        __syncthreads();
        gemm_t<64, true>(sHb, ST_H, sWr3, sHa, C_R,  e0, e1, cb);
        __syncthreads();
        l4_store(sHa, sWr4, g_tpw + (size_t)eg * 256, t);
    }
}

// ==== K_gather: CSR walk per node, atomic-free accumulation ====
__global__ __launch_bounds__(256) void k_gather(const float* __restrict__ ea,
                                                const int* __restrict__ src) {
    const int t = threadIdx.x;
    const int n = blockIdx.x * 4 + (t >> 6);
    const int u = t & 63;
    const int beg = g_rowptr[n], end = g_rowptr[n + 1];
    float m0a = 0.f, m0b = 0.f;
    float m1a0 = 0.f, m1a1 = 0.f, m1a2 = 0.f;
    float m1b0 = 0.f, m1b1 = 0.f, m1b2 = 0.f;
    for (int idx = beg; idx < end; idx++) {
        const int e = g_eid[idx];
        const float sh0 = __ldg(ea + (size_t)e * 4 + 0);
        const float a1  = __ldg(ea + (size_t)e * 4 + 1);
        const float a2  = __ldg(ea + (size_t)e * 4 + 2);
        const float a3  = __ldg(ea + (size_t)e * 4 + 3);
        const int sn = __ldg(src + e);
        const float* xr = g_x + (size_t)sn * 256;
        const float s  = xr[u];
        const float v0 = xr[64 + u * 3 + 0];
        const float v1 = xr[64 + u * 3 + 1];
        const float v2 = xr[64 + u * 3 + 2];
        const __half* tp = g_tpw + (size_t)e * 256;
        const float t0 = __half2float(tp[u]);
        const float t1 = __half2float(tp[64 + u]);
        const float t2 = __half2float(tp[128 + u]);
        const float t3 = __half2float(tp[192 + u]);
        m0a += t0 * s * sh0;
        const float dv = v0 * a1 + v1 * a2 + v2 * a3;
        m0b += t3 * dv * INV_SQRT3;
        const float ts = t1 * s;
        m1a0 += ts * a1; m1a1 += ts * a2; m1a2 += ts * a3;
        const float tv = t2 * sh0;
        m1b0 += tv * v0; m1b1 += tv * v1; m1b2 += tv * v2;
    }
    float* mr = g_m + (size_t)n * 512;
    mr[u] = m0a;
    mr[64 + u] = m0b;
    mr[128 + u * 3 + 0] = m1a0;
    mr[128 + u * 3 + 1] = m1a1;
    mr[128 + u * 3 + 2] = m1a2;
    mr[320 + u * 3 + 0] = m1b0;
    mr[320 + u * 3 + 1] = m1b1;
    mr[320 + u * 3 + 2] = m1b2;
}

// ==== K2: node output, 16 nodes/block (R3 proven version) ====
#define NOB 16
#define O2_WL0 0
#define O2_WL1 8192
#define O2_M   16384
#define O2_Y   24576
#define O2_A   28672
#define K2_SMEM_FLOATS (O2_A + 192)

__global__ __launch_bounds__(256, 2) void k_node_out(const float* __restrict__ na,
                                                     const float* __restrict__ Wl0,
                                                     const float* __restrict__ Wl1,
                                                     float* __restrict__ out) {
    extern __shared__ float sm[];
    float* sWl0 = sm + O2_WL0;
    float* sWl1 = sm + O2_WL1;
    float* sWt  = sm;                 // phase-B reuse (12288 floats)
    float* sM   = sm + O2_M;
    float* sY   = sm + O2_Y;
    float* sA   = sm + O2_A;
    const int t = threadIdx.x;
    const int n0 = blockIdx.x * NOB;
    for (int i = t; i < 8192; i += 256) { sWl0[i] = Wl0[i]; sWl1[i] = Wl1[i]; }
    for (int i = t; i < NOB * 512; i += 256) sM[i] = g_m[(size_t)n0 * 512 + i];
    for (int i = t; i < NOB * 12; i += 256) {
        int n = i / 12, w = i % 12;
        sA[i] = (w < 10) ? na[(size_t)(n0 + n) * 10 + w] : 0.f;
    }
    __syncthreads();
    const int n4 = t >> 6, u = t & 63;

    // ---- phase A: y = m @ W_lin ----
    float y[16];
    #pragma unroll
    for (int i = 0; i < 16; i++) y[i] = 0.f;
    #pragma unroll 4
    for (int v = 0; v < 128; v++) {
        float w0 = sWl0[v * 64 + u], w1 = sWl1[v * 64 + u];
        #pragma unroll
        for (int ns = 0; ns < 4; ns++) {
            const float* m = sM + (ns * 4 + n4) * 512;
            y[ns*4+0] += m[v] * w0;
            y[ns*4+1] += m[128 + v*3 + 0] * w1;
            y[ns*4+2] += m[128 + v*3 + 1] * w1;
            y[ns*4+3] += m[128 + v*3 + 2] * w1;
        }
    }
    #pragma unroll
    for (int ns = 0; ns < 4; ns++) {
        float* yb = sY + (ns * 4 + n4) * 256;
        yb[u]       = y[ns*4+0] * C_LIN;
        yb[64 + u]  = y[ns*4+1] * C_LIN;
        yb[128 + u] = y[ns*4+2] * C_LIN;
        yb[192 + u] = y[ns*4+3] * C_LIN;
    }
    float areg[40];
    #pragma unroll
    for (int ns = 0; ns < 4; ns++)
        #pragma unroll
        for (int w = 0; w < 10; w++)
            areg[ns*10 + w] = sA[(ns*4 + n4) * 12 + w];

    // ---- phase B: z = y . (a . W_skip), W_skip streamed via smem ----
    float z[16];
    #pragma unroll
    for (int i = 0; i < 16; i++) z[i] = 0.f;
    for (int vc = 0; vc < 8; vc++) {
        __syncthreads();
        const int v0 = vc * 8;
        const float4* g0p = (const float4*)(g_wt0 + (size_t)v0 * 768);
        const float4* g1p = (const float4*)(g_wt1 + (size_t)v0 * 768);
        float4* d0 = (float4*)sWt;
        float4* d1 = (float4*)(sWt + 6144);
        for (int i = t; i < 1536; i += 256) { d0[i] = g0p[i]; d1[i] = g1p[i]; }
        __syncthreads();
        #pragma unroll
        for (int v = 0; v < 8; v++) {
            const float* w0p = sWt + (v * 64 + u) * 12;
            const float* w1p = sWt + 6144 + (v * 64 + u) * 12;
            float4 wa0 = *(const float4*)(w0p);
            float4 wa1 = *(const float4*)(w0p + 4);
            float4 wa2 = *(const float4*)(w0p + 8);
            float4 wb0 = *(const float4*)(w1p);
            float4 wb1 = *(const float4*)(w1p + 4);
            float4 wb2 = *(const float4*)(w1p + 8);
            #pragma unroll
            for (int ns = 0; ns < 4; ns++) {
                const float* a = areg + ns * 10;
                float g0 = a[0]*wa0.x + a[1]*wa0.y + a[2]*wa0.z + a[3]*wa0.w
                         + a[4]*wa1.x + a[5]*wa1.y + a[6]*wa1.z + a[7]*wa1.w
                         + a[8]*wa2.x + a[9]*wa2.y;
                float g1 = a[0]*wb0.x + a[1]*wb0.y + a[2]*wb0.z + a[3]*wb0.w
                         + a[4]*wb1.x + a[5]*wb1.y + a[6]*wb1.z + a[7]*wb1.w
                         + a[8]*wb2.x + a[9]*wb2.y;
                const float* yp = sY + (ns * 4 + n4) * 256 + v0 + v;
                z[ns*4+0] += yp[0]   * g0;
                z[ns*4+1] += yp[64]  * g1;
                z[ns*4+2] += yp[128] * g1;
                z[ns*4+3] += yp[192] * g1;
            }
        }
    }
    #pragma unroll
    for (int ns = 0; ns < 4; ns++) {
        float* o = out + (size_t)(n0 + ns * 4 + n4) * 256;
        o[u]            = z[ns*4+0] * C_SKIP;
        o[64 + u*3 + 0] = z[ns*4+1] * C_SKIP;
        o[64 + u*3 + 1] = z[ns*4+2] * C_SKIP;
        o[64 + u*3 + 2] = z[ns*4+3] * C_SKIP;
    }
}

extern "C" void kernel_launch(void* const* d_in, const int* in_sizes, int n_in,
                              void* d_out, int out_size) {
    const float* nf  = (const float*)d_in[0];
    const float* na  = (const float*)d_in[1];
    const float* ef  = (const float*)d_in[2];
    const float* ea  = (const float*)d_in[3];
    const int*   src = (const int*)d_in[4];
    const int*   dst = (const int*)d_in[5];
    const float* Wu0 = (const float*)d_in[6];
    const float* Wu1 = (const float*)d_in[7];
    const float* Wr1 = (const float*)d_in[8];
    const float* Wr2 = (const float*)d_in[9];
    const float* Wr3 = (const float*)d_in[10];
    const float* Wr4 = (const float*)d_in[11];
    const float* Wl0 = (const float*)d_in[12];
    const float* Wl1 = (const float*)d_in[13];
    const float* Ws0 = (const float*)d_in[14];
    const float* Ws1 = (const float*)d_in[15];
    float* out = (float*)d_out;

    cudaFuncSetAttribute(k_edge_mlp, cudaFuncAttributeMaxDynamicSharedMemorySize,
                         K1_SMEM_FLOATS * 4);
    cudaFuncSetAttribute(k_node_out, cudaFuncAttributeMaxDynamicSharedMemorySize,
                         K2_SMEM_FLOATS * 4);

    void* cnt_ptr = nullptr;
    cudaGetSymbolAddress(&cnt_ptr, g_cnt);
    cudaMemsetAsync(cnt_ptr, 0, sizeof(int) * N_NODES, 0);

    // Launch order arranged so k_edge_mlp is the 5th launch (profiled slot):
    // memset(1), hist(2), scan(3), scatter(4), edge_mlp(5), node_up, prep, gather, node_out
    k_hist<<<N_EDGES / 256, 256>>>(dst);
    k_scan<<<1, 1024>>>();
    k_scatter<<<N_EDGES / 256, 256>>>(dst);
    k_edge_mlp<<<148, 512, K1_SMEM_FLOATS * 4>>>(ef, Wr1, Wr2, Wr3, Wr4);
    k_node_up<<<N_NODES / 8, 256>>>(nf, Wu0, Wu1);
    k_prep<<<192, 256>>>(Ws0, Ws1);
    k_gather<<<N_NODES / 4, 256>>>(ea, src);
    k_node_out<<<N_NODES / NOB, 256, K2_SMEM_FLOATS * 4>>>(na, Wl0, Wl1, out);
}

// round 13
// speedup vs baseline: 1.3764x; 1.3764x over previous
#include <cuda_runtime.h>
#include <cuda_fp16.h>
#include <cstdint>
#include <cstddef>

#define N_NODES 32768
#define N_EDGES 524288

// ---- scratch (device globals; allocations forbidden) ----
__device__ float  g_x[(size_t)N_NODES * 256];     // [0:64]=x0, [64+u*3+i]=x1[u][i]
__device__ float  g_m[(size_t)N_NODES * 512];     // [0:128]=m0, [128+v*3+i]=m1
__device__ __half g_tpw[(size_t)N_EDGES * 256];   // per-edge radial MLP output (fp16)
__device__ float  g_wt0[64 * 64 * 12];            // W_skip0 as [v][u][w-pad12]
__device__ float  g_wt1[64 * 64 * 12];
__device__ int    g_cnt[N_NODES];                 // histogram
__device__ int    g_cur[N_NODES];                 // scatter cursor
__device__ int    g_rowptr[N_NODES + 1];
__device__ int    g_eid[N_EDGES];

#define C_UP      0.125f
#define C_R1      0.35355339059327373f
#define C_R       0.125f
#define C_LIN     0.00552427172801990f
#define C_SKIP    0.03952847075210474f
#define INV_SQRT3 0.5773502691896258f

__device__ __forceinline__ float silu_f(float x) {
    return __fdividef(x, 1.0f + __expf(-x));
}
__device__ __forceinline__ unsigned int h2_bits(__half2 h) {
    return *reinterpret_cast<unsigned int*>(&h);
}

// ==== K_prep: W_skip (64,64,10)[u,v,w] -> [v][u][12] (w-padded) ====
__global__ void k_prep(const float* __restrict__ Ws0, const float* __restrict__ Ws1) {
    int idx = blockIdx.x * 256 + threadIdx.x;   // 0 .. 49151
    int v = idx / 768;
    int r = idx % 768;
    int u = r / 12, w = r % 12;
    float a = 0.f, b = 0.f;
    if (w < 10) {
        a = Ws0[u * 640 + v * 10 + w];
        b = Ws1[u * 640 + v * 10 + w];
    }
    g_wt0[idx] = a;
    g_wt1[idx] = b;
}

// ==== K0: node up-projection (8 nodes/block) ====
__global__ __launch_bounds__(256) void k_node_up(const float* __restrict__ nf,
                                                 const float* __restrict__ Wu0,
                                                 const float* __restrict__ Wu1) {
    __shared__ float sW0[4096], sW1[4096], sIn[2048];
    const int t = threadIdx.x;
    for (int i = t; i < 4096; i += 256) { sW0[i] = Wu0[i]; sW1[i] = Wu1[i]; }
    const int n0 = blockIdx.x * 8;
    for (int i = t; i < 2048; i += 256) sIn[i] = nf[(size_t)n0 * 256 + i];
    __syncthreads();
    const int j = t >> 6, u = t & 63;
    const int off0 = (j == 0) ? 0 : (63 + j);
    const int st = (j == 0) ? 1 : 3;
    const float* W = (j == 0) ? sW0 : sW1;
    const int oo = (j == 0) ? u : (64 + u * 3 + (j - 1));
    for (int c = 0; c < 2; c++) {
        float acc[4] = {0.f, 0.f, 0.f, 0.f};
        #pragma unroll 8
        for (int v = 0; v < 64; v++) {
            float w = W[v * 64 + u];
            #pragma unroll
            for (int r = 0; r < 4; r++)
                acc[r] += sIn[(c * 4 + r) * 256 + off0 + v * st] * w;
        }
        #pragma unroll
        for (int r = 0; r < 4; r++)
            g_x[(size_t)(n0 + c * 4 + r) * 256 + oo] = acc[r] * C_UP;
    }
}

// ==== CSR build over dst ====
__global__ void k_hist(const int* __restrict__ dst) {
    int e = blockIdx.x * 256 + threadIdx.x;
    atomicAdd(&g_cnt[dst[e]], 1);
}

__global__ __launch_bounds__(1024) void k_scan() {
    __shared__ int part[1024];
    const int t = threadIdx.x;
    int4 c4[8];
    const int4* cp = (const int4*)(g_cnt + t * 32);
    #pragma unroll
    for (int j = 0; j < 8; j++) c4[j] = cp[j];
    int vals[32];
    #pragma unroll
    for (int j = 0; j < 8; j++) {
        vals[j*4+0] = c4[j].x; vals[j*4+1] = c4[j].y;
        vals[j*4+2] = c4[j].z; vals[j*4+3] = c4[j].w;
    }
    int loc[32];
    int s = 0;
    #pragma unroll
    for (int j = 0; j < 32; j++) { loc[j] = s; s += vals[j]; }
    part[t] = s;
    __syncthreads();
    for (int off = 1; off < 1024; off <<= 1) {
        int v = (t >= off) ? part[t - off] : 0;
        __syncthreads();
        part[t] += v;
        __syncthreads();
    }
    int pre = (t == 0) ? 0 : part[t - 1];
    #pragma unroll
    for (int j = 0; j < 32; j++) {
        int o = pre + loc[j];
        g_rowptr[t * 32 + j] = o;
        g_cur[t * 32 + j] = o;
    }
    if (t == 1023) g_rowptr[N_NODES] = part[1023];
}

__global__ void k_scatter(const int* __restrict__ dst) {
    int e = blockIdx.x * 256 + threadIdx.x;
    int p = atomicAdd(&g_cur[dst[e]], 1);
    g_eid[p] = e;
}

// ==== K1: radial MLP only -> g_tpw (fp16). 512 threads, 128 edges/tile ====
#define ST_H 65
#define OFF_WR1 0
#define OFF_WR2 512
#define OFF_WR3 4608
#define OFF_WR4 8704
#define OFF_HA  25088
#define OFF_HB  (OFF_HA + 128*ST_H)       // 33408
#define OFF_EF  (OFF_HB + 128*ST_H)       // 41728
#define K1_SMEM_FLOATS (OFF_EF + 1024)    // 42752 floats -> 171008 B

template<int K, bool SILU>
__device__ __forceinline__ void gemm_t(const float* __restrict__ A, int astride,
                                       const float* __restrict__ B,
                                       float* __restrict__ O,
                                       float scale, int e0, int e1, int cb) {
    float acc[2][8];
    #pragma unroll
    for (int r = 0; r < 2; r++)
        #pragma unroll
        for (int j = 0; j < 8; j++) acc[r][j] = 0.f;
    #pragma unroll 8
    for (int k = 0; k < K; k++) {
        float a0 = A[e0 * astride + k];
        float a1 = A[e1 * astride + k];
        const float4 b0 = *(const float4*)(B + k * 64 + cb);
        const float4 b1 = *(const float4*)(B + k * 64 + cb + 4);
        acc[0][0] += a0*b0.x; acc[0][1] += a0*b0.y; acc[0][2] += a0*b0.z; acc[0][3] += a0*b0.w;
        acc[0][4] += a0*b1.x; acc[0][5] += a0*b1.y; acc[0][6] += a0*b1.z; acc[0][7] += a0*b1.w;
        acc[1][0] += a1*b0.x; acc[1][1] += a1*b0.y; acc[1][2] += a1*b0.z; acc[1][3] += a1*b0.w;
        acc[1][4] += a1*b1.x; acc[1][5] += a1*b1.y; acc[1][6] += a1*b1.z; acc[1][7] += a1*b1.w;
    }
    #pragma unroll
    for (int r = 0; r < 2; r++) {
        const int e = r ? e1 : e0;
        #pragma unroll
        for (int j = 0; j < 8; j++) {
            float x = acc[r][j] * scale;
            O[e * ST_H + cb + j] = SILU ? silu_f(x) : x;
        }
    }
}

// L4: 4 edges x 16 cols per thread, CONFLICT-FREE column mapping:
// thread owns cols {c4..c4+3} in each of the four 64-col chunks (c4=(t&15)*4),
// so lanes 0-15 cover 64 contiguous floats per LDS.128 (no bank conflicts).
__device__ __forceinline__ void l4_store(const float* __restrict__ H,
                                         const float* __restrict__ W4,
                                         __half* __restrict__ gout,
                                         int t) {
    const int tg = t >> 4;           // 0..31 -> edges 4tg..4tg+3
    const int c4 = (t & 15) * 4;     // col base within each 64-chunk
    float acc[4][16];                // [edge][cc*4+j]
    #pragma unroll
    for (int i = 0; i < 4; i++)
        #pragma unroll
        for (int j = 0; j < 16; j++) acc[i][j] = 0.f;
    #pragma unroll 4
    for (int k = 0; k < 64; k++) {
        float a[4];
        #pragma unroll
        for (int i = 0; i < 4; i++) a[i] = H[(4*tg + i) * ST_H + k];
        #pragma unroll
        for (int cc = 0; cc < 4; cc++) {
            const float4 b = *(const float4*)(W4 + k * 256 + cc * 64 + c4);
            #pragma unroll
            for (int i = 0; i < 4; i++) {
                acc[i][cc*4+0] += a[i]*b.x;
                acc[i][cc*4+1] += a[i]*b.y;
                acc[i][cc*4+2] += a[i]*b.z;
                acc[i][cc*4+3] += a[i]*b.w;
            }
        }
    }
    #pragma unroll
    for (int i = 0; i < 4; i++) {
        #pragma unroll
        for (int cc = 0; cc < 4; cc++) {
            __half2 lo = __floats2half2_rn(acc[i][cc*4+0]*C_R, acc[i][cc*4+1]*C_R);
            __half2 hi = __floats2half2_rn(acc[i][cc*4+2]*C_R, acc[i][cc*4+3]*C_R);
            uint2 pk;
            pk.x = h2_bits(lo);
            pk.y = h2_bits(hi);
            *(uint2*)(gout + (size_t)(4*tg + i) * 256 + cc * 64 + c4) = pk;
        }
    }
}

__global__ __launch_bounds__(512, 1) void k_edge_mlp(const float* __restrict__ ef,
                                                     const float* __restrict__ Wr1,
                                                     const float* __restrict__ Wr2,
                                                     const float* __restrict__ Wr3,
                                                     const float* __restrict__ Wr4) {
    extern __shared__ float sm[];
    float* sWr1 = sm + OFF_WR1;
    float* sWr2 = sm + OFF_WR2;
    float* sWr3 = sm + OFF_WR3;
    float* sWr4 = sm + OFF_WR4;
    float* sHa  = sm + OFF_HA;
    float* sHb  = sm + OFF_HB;
    float* sEF  = sm + OFF_EF;
    const int t = threadIdx.x;
    if (t < 512) sWr1[t] = Wr1[t];
    for (int i = t; i < 4096;  i += 512) { sWr2[i] = Wr2[i]; sWr3[i] = Wr3[i]; }
    for (int i = t; i < 16384; i += 512) sWr4[i] = Wr4[i];
    const int te = t >> 3, tc = t & 7;
    const int e0 = te * 2, e1 = te * 2 + 1, cb = tc * 8;

    for (int tile = blockIdx.x; tile < N_EDGES / 128; tile += gridDim.x) {
        const int eg = tile * 128;
        __syncthreads();
        for (int i = t; i < 1024; i += 512) sEF[i] = ef[(size_t)eg * 8 + i];
        __syncthreads();
        gemm_t<8,  true>(sEF, 8,    sWr1, sHa, C_R1, e0, e1, cb);
        __syncthreads();
        gemm_t<64, true>(sHa, ST_H, sWr2, sHb, C_R,  e0, e1, cb);
        __syncthreads();
        gemm_t<64, true>(sHb, ST_H, sWr3, sHa, C_R,  e0, e1, cb);
        __syncthreads();
        l4_store(sHa, sWr4, g_tpw + (size_t)eg * 256, t);
    }
}

// ==== K_gather: CSR walk per node, atomic-free accumulation ====
__global__ __launch_bounds__(256) void k_gather(const float* __restrict__ ea,
                                                const int* __restrict__ src) {
    const int t = threadIdx.x;
    const int n = blockIdx.x * 4 + (t >> 6);
    const int u = t & 63;
    const int beg = g_rowptr[n], end = g_rowptr[n + 1];
    float m0a = 0.f, m0b = 0.f;
    float m1a0 = 0.f, m1a1 = 0.f, m1a2 = 0.f;
    float m1b0 = 0.f, m1b1 = 0.f, m1b2 = 0.f;
    for (int idx = beg; idx < end; idx++) {
        const int e = g_eid[idx];
        const float sh0 = __ldg(ea + (size_t)e * 4 + 0);
        const float a1  = __ldg(ea + (size_t)e * 4 + 1);
        const float a2  = __ldg(ea + (size_t)e * 4 + 2);
        const float a3  = __ldg(ea + (size_t)e * 4 + 3);
        const int sn = __ldg(src + e);
        const float* xr = g_x + (size_t)sn * 256;
        const float s  = xr[u];
        const float v0 = xr[64 + u * 3 + 0];
        const float v1 = xr[64 + u * 3 + 1];
        const float v2 = xr[64 + u * 3 + 2];
        const __half* tp = g_tpw + (size_t)e * 256;
        const float t0 = __half2float(tp[u]);
        const float t1 = __half2float(tp[64 + u]);
        const float t2 = __half2float(tp[128 + u]);
        const float t3 = __half2float(tp[192 + u]);
        m0a += t0 * s * sh0;
        const float dv = v0 * a1 + v1 * a2 + v2 * a3;
        m0b += t3 * dv * INV_SQRT3;
        const float ts = t1 * s;
        m1a0 += ts * a1; m1a1 += ts * a2; m1a2 += ts * a3;
        const float tv = t2 * sh0;
        m1b0 += tv * v0; m1b1 += tv * v1; m1b2 += tv * v2;
    }
    float* mr = g_m + (size_t)n * 512;
    mr[u] = m0a;
    mr[64 + u] = m0b;
    mr[128 + u * 3 + 0] = m1a0;
    mr[128 + u * 3 + 1] = m1a1;
    mr[128 + u * 3 + 2] = m1a2;
    mr[320 + u * 3 + 0] = m1b0;
    mr[320 + u * 3 + 1] = m1b1;
    mr[320 + u * 3 + 2] = m1b2;
}

// ==== K2: node output, 16 nodes/block (R3 proven version) ====
#define NOB 16
#define O2_WL0 0
#define O2_WL1 8192
#define O2_M   16384
#define O2_Y   24576
#define O2_A   28672
#define K2_SMEM_FLOATS (O2_A + 192)

__global__ __launch_bounds__(256, 2) void k_node_out(const float* __restrict__ na,
                                                     const float* __restrict__ Wl0,
                                                     const float* __restrict__ Wl1,
                                                     float* __restrict__ out) {
    extern __shared__ float sm[];
    float* sWl0 = sm + O2_WL0;
    float* sWl1 = sm + O2_WL1;
    float* sWt  = sm;                 // phase-B reuse (12288 floats)
    float* sM   = sm + O2_M;
    float* sY   = sm + O2_Y;
    float* sA   = sm + O2_A;
    const int t = threadIdx.x;
    const int n0 = blockIdx.x * NOB;
    for (int i = t; i < 8192; i += 256) { sWl0[i] = Wl0[i]; sWl1[i] = Wl1[i]; }
    for (int i = t; i < NOB * 512; i += 256) sM[i] = g_m[(size_t)n0 * 512 + i];
    for (int i = t; i < NOB * 12; i += 256) {
        int n = i / 12, w = i % 12;
        sA[i] = (w < 10) ? na[(size_t)(n0 + n) * 10 + w] : 0.f;
    }
    __syncthreads();
    const int n4 = t >> 6, u = t & 63;

    // ---- phase A: y = m @ W_lin ----
    float y[16];
    #pragma unroll
    for (int i = 0; i < 16; i++) y[i] = 0.f;
    #pragma unroll 4
    for (int v = 0; v < 128; v++) {
        float w0 = sWl0[v * 64 + u], w1 = sWl1[v * 64 + u];
        #pragma unroll
        for (int ns = 0; ns < 4; ns++) {
            const float* m = sM + (ns * 4 + n4) * 512;
            y[ns*4+0] += m[v] * w0;
            y[ns*4+1] += m[128 + v*3 + 0] * w1;
            y[ns*4+2] += m[128 + v*3 + 1] * w1;
            y[ns*4+3] += m[128 + v*3 + 2] * w1;
        }
    }
    #pragma unroll
    for (int ns = 0; ns < 4; ns++) {
        float* yb = sY + (ns * 4 + n4) * 256;
        yb[u]       = y[ns*4+0] * C_LIN;
        yb[64 + u]  = y[ns*4+1] * C_LIN;
        yb[128 + u] = y[ns*4+2] * C_LIN;
        yb[192 + u] = y[ns*4+3] * C_LIN;
    }
    float areg[40];
    #pragma unroll
    for (int ns = 0; ns < 4; ns++)
        #pragma unroll
        for (int w = 0; w < 10; w++)
            areg[ns*10 + w] = sA[(ns*4 + n4) * 12 + w];

    // ---- phase B: z = y . (a . W_skip), W_skip streamed via smem ----
    float z[16];
    #pragma unroll
    for (int i = 0; i < 16; i++) z[i] = 0.f;
    for (int vc = 0; vc < 8; vc++) {
        __syncthreads();
        const int v0 = vc * 8;
        const float4* g0p = (const float4*)(g_wt0 + (size_t)v0 * 768);
        const float4* g1p = (const float4*)(g_wt1 + (size_t)v0 * 768);
        float4* d0 = (float4*)sWt;
        float4* d1 = (float4*)(sWt + 6144);
        for (int i = t; i < 1536; i += 256) { d0[i] = g0p[i]; d1[i] = g1p[i]; }
        __syncthreads();
        #pragma unroll
        for (int v = 0; v < 8; v++) {
            const float* w0p = sWt + (v * 64 + u) * 12;
            const float* w1p = sWt + 6144 + (v * 64 + u) * 12;
            float4 wa0 = *(const float4*)(w0p);
            float4 wa1 = *(const float4*)(w0p + 4);
            float4 wa2 = *(const float4*)(w0p + 8);
            float4 wb0 = *(const float4*)(w1p);
            float4 wb1 = *(const float4*)(w1p + 4);
            float4 wb2 = *(const float4*)(w1p + 8);
            #pragma unroll
            for (int ns = 0; ns < 4; ns++) {
                const float* a = areg + ns * 10;
                float g0 = a[0]*wa0.x + a[1]*wa0.y + a[2]*wa0.z + a[3]*wa0.w
                         + a[4]*wa1.x + a[5]*wa1.y + a[6]*wa1.z + a[7]*wa1.w
                         + a[8]*wa2.x + a[9]*wa2.y;
                float g1 = a[0]*wb0.x + a[1]*wb0.y + a[2]*wb0.z + a[3]*wb0.w
                         + a[4]*wb1.x + a[5]*wb1.y + a[6]*wb1.z + a[7]*wb1.w
                         + a[8]*wb2.x + a[9]*wb2.y;
                const float* yp = sY + (ns * 4 + n4) * 256 + v0 + v;
                z[ns*4+0] += yp[0]   * g0;
                z[ns*4+1] += yp[64]  * g1;
                z[ns*4+2] += yp[128] * g1;
                z[ns*4+3] += yp[192] * g1;
            }
        }
    }
    #pragma unroll
    for (int ns = 0; ns < 4; ns++) {
        float* o = out + (size_t)(n0 + ns * 4 + n4) * 256;
        o[u]            = z[ns*4+0] * C_SKIP;
        o[64 + u*3 + 0] = z[ns*4+1] * C_SKIP;
        o[64 + u*3 + 1] = z[ns*4+2] * C_SKIP;
        o[64 + u*3 + 2] = z[ns*4+3] * C_SKIP;
    }
}

extern "C" void kernel_launch(void* const* d_in, const int* in_sizes, int n_in,
                              void* d_out, int out_size) {
    const float* nf  = (const float*)d_in[0];
    const float* na  = (const float*)d_in[1];
    const float* ef  = (const float*)d_in[2];
    const float* ea  = (const float*)d_in[3];
    const int*   src = (const int*)d_in[4];
    const int*   dst = (const int*)d_in[5];
    const float* Wu0 = (const float*)d_in[6];
    const float* Wu1 = (const float*)d_in[7];
    const float* Wr1 = (const float*)d_in[8];
    const float* Wr2 = (const float*)d_in[9];
    const float* Wr3 = (const float*)d_in[10];
    const float* Wr4 = (const float*)d_in[11];
    const float* Wl0 = (const float*)d_in[12];
    const float* Wl1 = (const float*)d_in[13];
    const float* Ws0 = (const float*)d_in[14];
    const float* Ws1 = (const float*)d_in[15];
    float* out = (float*)d_out;

    cudaFuncSetAttribute(k_edge_mlp, cudaFuncAttributeMaxDynamicSharedMemorySize,
                         K1_SMEM_FLOATS * 4);
    cudaFuncSetAttribute(k_node_out, cudaFuncAttributeMaxDynamicSharedMemorySize,
                         K2_SMEM_FLOATS * 4);

    void* cnt_ptr = nullptr;
    cudaGetSymbolAddress(&cnt_ptr, g_cnt);
    cudaMemsetAsync(cnt_ptr, 0, sizeof(int) * N_NODES, 0);

    // Launch order keeps k_edge_mlp in the profiled (5th) slot:
    // memset(1), hist(2), scan(3), scatter(4), edge_mlp(5), node_up, prep, gather, node_out
    k_hist<<<N_EDGES / 256, 256>>>(dst);
    k_scan<<<1, 1024>>>();
    k_scatter<<<N_EDGES / 256, 256>>>(dst);
    k_edge_mlp<<<148, 512, K1_SMEM_FLOATS * 4>>>(ef, Wr1, Wr2, Wr3, Wr4);
    k_node_up<<<N_NODES / 8, 256>>>(nf, Wu0, Wu1);
    k_prep<<<192, 256>>>(Ws0, Ws1);
    k_gather<<<N_NODES / 4, 256>>>(ea, src);
    k_node_out<<<N_NODES / NOB, 256, K2_SMEM_FLOATS * 4>>>(na, Wl0, Wl1, out);
}

// round 16
// speedup vs baseline: 1.5832x; 1.1502x over previous
#include <cuda_runtime.h>
#include <cuda_fp16.h>
#include <cstdint>
#include <cstddef>

#define N_NODES 32768
#define N_EDGES 524288

// ---- scratch (device globals; allocations forbidden) ----
__device__ float  g_x[(size_t)N_NODES * 256];     // [0:64]=x0, [64+u*3+i]=x1[u][i]
__device__ float  g_m[(size_t)N_NODES * 512];     // [0:128]=m0, [128+v*3+i]=m1
__device__ __half g_tpw[(size_t)N_EDGES * 256];   // per-edge radial MLP output (fp16)
__device__ float  g_wt0[64 * 640];                // W_skip0 as [v][w][u]
__device__ float  g_wt1[64 * 640];
__device__ int    g_cnt[N_NODES];
__device__ int    g_cur[N_NODES];
__device__ int    g_rowptr[N_NODES + 1];
__device__ int    g_eid[N_EDGES];

#define C_UP      0.125f
#define C_R1      0.35355339059327373f
#define C_R       0.125f
#define C_LIN     0.00552427172801990f
#define C_SKIP    0.03952847075210474f
#define INV_SQRT3 0.5773502691896258f

__device__ __forceinline__ float silu_f(float x) {
    return __fdividef(x, 1.0f + __expf(-x));
}
__device__ __forceinline__ unsigned int h2_bits(__half2 h) {
    return *reinterpret_cast<unsigned int*>(&h);
}

// ==== K_prep: W_skip (64,64,10)[u,v,w] -> [v][w][u] ====
__global__ void k_prep(const float* __restrict__ Ws0, const float* __restrict__ Ws1) {
    int idx = blockIdx.x * 256 + threadIdx.x;   // 0..40959
    int v = idx / 640, r = idx % 640;
    int w = r / 64, u = r % 64;
    g_wt0[idx] = Ws0[u * 640 + v * 10 + w];
    g_wt1[idx] = Ws1[u * 640 + v * 10 + w];
}

// ==== K0: node up-projection (8 nodes/block) ====
__global__ __launch_bounds__(256) void k_node_up(const float* __restrict__ nf,
                                                 const float* __restrict__ Wu0,
                                                 const float* __restrict__ Wu1) {
    __shared__ float sW0[4096], sW1[4096], sIn[2048];
    const int t = threadIdx.x;
    for (int i = t; i < 4096; i += 256) { sW0[i] = Wu0[i]; sW1[i] = Wu1[i]; }
    const int n0 = blockIdx.x * 8;
    for (int i = t; i < 2048; i += 256) sIn[i] = nf[(size_t)n0 * 256 + i];
    __syncthreads();
    const int j = t >> 6, u = t & 63;
    const int off0 = (j == 0) ? 0 : (63 + j);
    const int st = (j == 0) ? 1 : 3;
    const float* W = (j == 0) ? sW0 : sW1;
    const int oo = (j == 0) ? u : (64 + u * 3 + (j - 1));
    for (int c = 0; c < 2; c++) {
        float acc[4] = {0.f, 0.f, 0.f, 0.f};
        #pragma unroll 8
        for (int v = 0; v < 64; v++) {
            float w = W[v * 64 + u];
            #pragma unroll
            for (int r = 0; r < 4; r++)
                acc[r] += sIn[(c * 4 + r) * 256 + off0 + v * st] * w;
        }
        #pragma unroll
        for (int r = 0; r < 4; r++)
            g_x[(size_t)(n0 + c * 4 + r) * 256 + oo] = acc[r] * C_UP;
    }
}

// ==== CSR build over dst ====
__global__ void k_hist(const int* __restrict__ dst) {
    int e = blockIdx.x * 256 + threadIdx.x;
    atomicAdd(&g_cnt[dst[e]], 1);
}

__global__ __launch_bounds__(1024) void k_scan() {
    __shared__ int part[1024];
    const int t = threadIdx.x;
    int4 c4[8];
    const int4* cp = (const int4*)(g_cnt + t * 32);
    #pragma unroll
    for (int j = 0; j < 8; j++) c4[j] = cp[j];
    int vals[32];
    #pragma unroll
    for (int j = 0; j < 8; j++) {
        vals[j*4+0] = c4[j].x; vals[j*4+1] = c4[j].y;
        vals[j*4+2] = c4[j].z; vals[j*4+3] = c4[j].w;
    }
    int loc[32];
    int s = 0;
    #pragma unroll
    for (int j = 0; j < 32; j++) { loc[j] = s; s += vals[j]; }
    part[t] = s;
    __syncthreads();
    for (int off = 1; off < 1024; off <<= 1) {
        int v = (t >= off) ? part[t - off] : 0;
        __syncthreads();
        part[t] += v;
        __syncthreads();
    }
    int pre = (t == 0) ? 0 : part[t - 1];
    #pragma unroll
    for (int j = 0; j < 32; j++) {
        int o = pre + loc[j];
        g_rowptr[t * 32 + j] = o;
        g_cur[t * 32 + j] = o;
    }
    if (t == 1023) g_rowptr[N_NODES] = part[1023];
}

__global__ void k_scatter(const int* __restrict__ dst) {
    int e = blockIdx.x * 256 + threadIdx.x;
    int p = atomicAdd(&g_cur[dst[e]], 1);
    g_eid[p] = e;
}

// ==== K1: radial MLP only -> g_tpw (fp16). 512 threads, 128 edges/tile ====
#define ST_H 68
#define OFF_WR1 0
#define OFF_WR2 512
#define OFF_WR3 4608
#define OFF_WR4 8704
#define OFF_HA  25088
#define OFF_HB  (OFF_HA + 128*ST_H)       // 33792
#define OFF_EF  (OFF_HB + 128*ST_H)       // 42496
#define K1_SMEM_FLOATS (OFF_EF + 1024)    // 43520 floats -> 174080 B

// Layers 1-3: thread owns cols {c4..c4+3} and {32+c4..32+c4+3} (c4=(t&7)*4).
// B LDS.128: warp covers one contiguous 128B region per load -> conflict-free.
// O STS.128 (ST_H=68): edge bases {0,8,16,24} mod 32, 8 banks each -> conflict-free.
template<int K, bool SILU>
__device__ __forceinline__ void gemm_t(const float* __restrict__ A, int astride,
                                       const float* __restrict__ B,
                                       float* __restrict__ O,
                                       float scale, int e0, int e1, int c4) {
    float acc[2][8];   // [edge][0..3]=cols c4.., [4..7]=cols 32+c4..
    #pragma unroll
    for (int r = 0; r < 2; r++)
        #pragma unroll
        for (int j = 0; j < 8; j++) acc[r][j] = 0.f;
    #pragma unroll 8
    for (int k = 0; k < K; k++) {
        float a0 = A[e0 * astride + k];
        float a1 = A[e1 * astride + k];
        const float4 bl = *(const float4*)(B + k * 64 + c4);
        const float4 bh = *(const float4*)(B + k * 64 + 32 + c4);
        acc[0][0] += a0*bl.x; acc[0][1] += a0*bl.y; acc[0][2] += a0*bl.z; acc[0][3] += a0*bl.w;
        acc[0][4] += a0*bh.x; acc[0][5] += a0*bh.y; acc[0][6] += a0*bh.z; acc[0][7] += a0*bh.w;
        acc[1][0] += a1*bl.x; acc[1][1] += a1*bl.y; acc[1][2] += a1*bl.z; acc[1][3] += a1*bl.w;
        acc[1][4] += a1*bh.x; acc[1][5] += a1*bh.y; acc[1][6] += a1*bh.z; acc[1][7] += a1*bh.w;
    }
    #pragma unroll
    for (int r = 0; r < 2; r++) {
        const int e = r ? e1 : e0;
        float v[8];
        #pragma unroll
        for (int j = 0; j < 8; j++) {
            float x = acc[r][j] * scale;
            v[j] = SILU ? silu_f(x) : x;
        }
        *(float4*)(O + e * ST_H + c4)      = make_float4(v[0], v[1], v[2], v[3]);
        *(float4*)(O + e * ST_H + 32 + c4) = make_float4(v[4], v[5], v[6], v[7]);
    }
}

// L4: 4 edges x 16 cols per thread, conflict-free (from R12).
__device__ __forceinline__ void l4_store(const float* __restrict__ H,
                                         const float* __restrict__ W4,
                                         __half* __restrict__ gout,
                                         int t) {
    const int tg = t >> 4;
    const int c4 = (t & 15) * 4;
    float acc[4][16];
    #pragma unroll
    for (int i = 0; i < 4; i++)
        #pragma unroll
        for (int j = 0; j < 16; j++) acc[i][j] = 0.f;
    #pragma unroll 4
    for (int k = 0; k < 64; k++) {
        float a[4];
        #pragma unroll
        for (int i = 0; i < 4; i++) a[i] = H[(4*tg + i) * ST_H + k];
        #pragma unroll
        for (int cc = 0; cc < 4; cc++) {
            const float4 b = *(const float4*)(W4 + k * 256 + cc * 64 + c4);
            #pragma unroll
            for (int i = 0; i < 4; i++) {
                acc[i][cc*4+0] += a[i]*b.x;
                acc[i][cc*4+1] += a[i]*b.y;
                acc[i][cc*4+2] += a[i]*b.z;
                acc[i][cc*4+3] += a[i]*b.w;
            }
        }
    }
    #pragma unroll
    for (int i = 0; i < 4; i++) {
        #pragma unroll
        for (int cc = 0; cc < 4; cc++) {
            __half2 lo = __floats2half2_rn(acc[i][cc*4+0]*C_R, acc[i][cc*4+1]*C_R);
            __half2 hi = __floats2half2_rn(acc[i][cc*4+2]*C_R, acc[i][cc*4+3]*C_R);
            uint2 pk;
            pk.x = h2_bits(lo);
            pk.y = h2_bits(hi);
            *(uint2*)(gout + (size_t)(4*tg + i) * 256 + cc * 64 + c4) = pk;
        }
    }
}

__global__ __launch_bounds__(512, 1) void k_edge_mlp(const float* __restrict__ ef,
                                                     const float* __restrict__ Wr1,
                                                     const float* __restrict__ Wr2,
                                                     const float* __restrict__ Wr3,
                                                     const float* __restrict__ Wr4) {
    extern __shared__ float sm[];
    float* sWr1 = sm + OFF_WR1;
    float* sWr2 = sm + OFF_WR2;
    float* sWr3 = sm + OFF_WR3;
    float* sWr4 = sm + OFF_WR4;
    float* sHa  = sm + OFF_HA;
    float* sHb  = sm + OFF_HB;
    float* sEF  = sm + OFF_EF;
    const int t = threadIdx.x;
    if (t < 512) sWr1[t] = Wr1[t];
    for (int i = t; i < 4096;  i += 512) { sWr2[i] = Wr2[i]; sWr3[i] = Wr3[i]; }
    for (int i = t; i < 16384; i += 512) sWr4[i] = Wr4[i];
    const int te = t >> 3, tc = t & 7;
    const int e0 = te * 2, e1 = te * 2 + 1, c4 = tc * 4;

    for (int tile = blockIdx.x; tile < N_EDGES / 128; tile += gridDim.x) {
        const int eg = tile * 128;
        __syncthreads();
        for (int i = t; i < 1024; i += 512) sEF[i] = ef[(size_t)eg * 8 + i];
        __syncthreads();
        gemm_t<8,  true>(sEF, 8,    sWr1, sHa, C_R1, e0, e1, c4);
        __syncthreads();
        gemm_t<64, true>(sHa, ST_H, sWr2, sHb, C_R,  e0, e1, c4);
        __syncthreads();
        gemm_t<64, true>(sHb, ST_H, sWr3, sHa, C_R,  e0, e1, c4);
        __syncthreads();
        l4_store(sHa, sWr4, g_tpw + (size_t)eg * 256, t);
    }
}

// ==== K_gather: CSR walk per node; ea via LDG.128; eid prefetch ====
__global__ __launch_bounds__(256) void k_gather(const float* __restrict__ ea,
                                                const int* __restrict__ src) {
    const int t = threadIdx.x;
    const int n = blockIdx.x * 4 + (t >> 6);
    const int u = t & 63;
    const int beg = g_rowptr[n], end = g_rowptr[n + 1];
    float m0a = 0.f, m0b = 0.f;
    float m1a0 = 0.f, m1a1 = 0.f, m1a2 = 0.f;
    float m1b0 = 0.f, m1b1 = 0.f, m1b2 = 0.f;
    if (beg < end) {
        int e = __ldg(g_eid + beg);
        for (int idx = beg; idx < end; idx++) {
            const int e_nx = (idx + 1 < end) ? __ldg(g_eid + idx + 1) : 0;
            const float4 av = __ldg((const float4*)(ea + (size_t)e * 4));
            const int sn = __ldg(src + e);
            const float sh0 = av.x, a1 = av.y, a2 = av.z, a3 = av.w;
            const float* xr = g_x + (size_t)sn * 256;
            const float s  = xr[u];
            const float v0 = xr[64 + u * 3 + 0];
            const float v1 = xr[64 + u * 3 + 1];
            const float v2 = xr[64 + u * 3 + 2];
            const __half* tp = g_tpw + (size_t)e * 256;
            const float t0 = __half2float(tp[u]);
            const float t1 = __half2float(tp[64 + u]);
            const float t2 = __half2float(tp[128 + u]);
            const float t3 = __half2float(tp[192 + u]);
            m0a += t0 * s * sh0;
            const float dv = v0 * a1 + v1 * a2 + v2 * a3;
            m0b += t3 * dv * INV_SQRT3;
            const float ts = t1 * s;
            m1a0 += ts * a1; m1a1 += ts * a2; m1a2 += ts * a3;
            const float tv = t2 * sh0;
            m1b0 += tv * v0; m1b1 += tv * v1; m1b2 += tv * v2;
            e = e_nx;
        }
    }
    float* mr = g_m + (size_t)n * 512;
    mr[u] = m0a;
    mr[64 + u] = m0b;
    mr[128 + u * 3 + 0] = m1a0;
    mr[128 + u * 3 + 1] = m1a1;
    mr[128 + u * 3 + 2] = m1a2;
    mr[320 + u * 3 + 0] = m1b0;
    mr[320 + u * 3 + 1] = m1b1;
    mr[320 + u * 3 + 2] = m1b2;
}

// ==== K2: node output, 16 nodes/block; phase-B uses [v][w][u] broadcast ====
#define NOB 16
#define O2_WL0 0
#define O2_WL1 8192
#define O2_M   16384
#define O2_Y   24576
#define O2_A   28672
#define K2_SMEM_FLOATS (O2_A + 192)

__global__ __launch_bounds__(256, 2) void k_node_out(const float* __restrict__ na,
                                                     const float* __restrict__ Wl0,
                                                     const float* __restrict__ Wl1,
                                                     float* __restrict__ out) {
    extern __shared__ float sm[];
    float* sWl0 = sm + O2_WL0;
    float* sWl1 = sm + O2_WL1;
    float* sWt  = sm;                 // phase-B reuse (needs 10240 floats)
    float* sM   = sm + O2_M;
    float* sY   = sm + O2_Y;
    float* sA   = sm + O2_A;
    const int t = threadIdx.x;
    const int n0 = blockIdx.x * NOB;
    for (int i = t; i < 8192; i += 256) { sWl0[i] = Wl0[i]; sWl1[i] = Wl1[i]; }
    for (int i = t; i < NOB * 512; i += 256) sM[i] = g_m[(size_t)n0 * 512 + i];
    for (int i = t; i < NOB * 12; i += 256) {
        int n = i / 12, w = i % 12;
        sA[i] = (w < 10) ? na[(size_t)(n0 + n) * 10 + w] : 0.f;
    }
    __syncthreads();
    const int n4 = t >> 6, u = t & 63;

    // ---- phase A: y = m @ W_lin ----
    float y[16];
    #pragma unroll
    for (int i = 0; i < 16; i++) y[i] = 0.f;
    #pragma unroll 4
    for (int v = 0; v < 128; v++) {
        float w0 = sWl0[v * 64 + u], w1 = sWl1[v * 64 + u];
        #pragma unroll
        for (int ns = 0; ns < 4; ns++) {
            const float* m = sM + (ns * 4 + n4) * 512;
            y[ns*4+0] += m[v] * w0;
            y[ns*4+1] += m[128 + v*3 + 0] * w1;
            y[ns*4+2] += m[128 + v*3 + 1] * w1;
            y[ns*4+3] += m[128 + v*3 + 2] * w1;
        }
    }
    #pragma unroll
    for (int ns = 0; ns < 4; ns++) {
        float* yb = sY + (ns * 4 + n4) * 256;
        yb[u]       = y[ns*4+0] * C_LIN;
        yb[64 + u]  = y[ns*4+1] * C_LIN;
        yb[128 + u] = y[ns*4+2] * C_LIN;
        yb[192 + u] = y[ns*4+3] * C_LIN;
    }
    float areg[40];
    #pragma unroll
    for (int ns = 0; ns < 4; ns++)
        #pragma unroll
        for (int w = 0; w < 10; w++)
            areg[ns*10 + w] = sA[(ns*4 + n4) * 12 + w];

    // ---- phase B: z = y . (a . W_skip); [v][w][u] -> broadcast scalar LDS ----
    float z[16];
    #pragma unroll
    for (int i = 0; i < 16; i++) z[i] = 0.f;
    for (int vc = 0; vc < 8; vc++) {
        __syncthreads();
        const int v0 = vc * 8;
        const float4* g0p = (const float4*)(g_wt0 + (size_t)v0 * 640);
        const float4* g1p = (const float4*)(g_wt1 + (size_t)v0 * 640);
        float4* d0 = (float4*)sWt;
        float4* d1 = (float4*)(sWt + 5120);
        for (int i = t; i < 1280; i += 256) { d0[i] = g0p[i]; d1[i] = g1p[i]; }
        __syncthreads();
        #pragma unroll
        for (int v = 0; v < 8; v++) {
            const float* w0b = sWt + v * 640 + u;
            const float* w1b = sWt + 5120 + v * 640 + u;
            float g0[4] = {0.f, 0.f, 0.f, 0.f}, g1[4] = {0.f, 0.f, 0.f, 0.f};
            #pragma unroll
            for (int w = 0; w < 10; w++) {
                float lw0 = w0b[w * 64];
                float lw1 = w1b[w * 64];
                #pragma unroll
                for (int ns = 0; ns < 4; ns++) {
                    g0[ns] += areg[ns*10 + w] * lw0;
                    g1[ns] += areg[ns*10 + w] * lw1;
                }
            }
            #pragma unroll
            for (int ns = 0; ns < 4; ns++) {
                const float* yp = sY + (ns * 4 + n4) * 256 + v0 + v;
                z[ns*4+0] += yp[0]   * g0[ns];
                z[ns*4+1] += yp[64]  * g1[ns];
                z[ns*4+2] += yp[128] * g1[ns];
                z[ns*4+3] += yp[192] * g1[ns];
            }
        }
    }
    #pragma unroll
    for (int ns = 0; ns < 4; ns++) {
        float* o = out + (size_t)(n0 + ns * 4 + n4) * 256;
        o[u]            = z[ns*4+0] * C_SKIP;
        o[64 + u*3 + 0] = z[ns*4+1] * C_SKIP;
        o[64 + u*3 + 1] = z[ns*4+2] * C_SKIP;
        o[64 + u*3 + 2] = z[ns*4+3] * C_SKIP;
    }
}

extern "C" void kernel_launch(void* const* d_in, const int* in_sizes, int n_in,
                              void* d_out, int out_size) {
    const float* nf  = (const float*)d_in[0];
    const float* na  = (const float*)d_in[1];
    const float* ef  = (const float*)d_in[2];
    const float* ea  = (const float*)d_in[3];
    const int*   src = (const int*)d_in[4];
    const int*   dst = (const int*)d_in[5];
    const float* Wu0 = (const float*)d_in[6];
    const float* Wu1 = (const float*)d_in[7];
    const float* Wr1 = (const float*)d_in[8];
    const float* Wr2 = (const float*)d_in[9];
    const float* Wr3 = (const float*)d_in[10];
    const float* Wr4 = (const float*)d_in[11];
    const float* Wl0 = (const float*)d_in[12];
    const float* Wl1 = (const float*)d_in[13];
    const float* Ws0 = (const float*)d_in[14];
    const float* Ws1 = (const float*)d_in[15];
    float* out = (float*)d_out;

    cudaFuncSetAttribute(k_edge_mlp, cudaFuncAttributeMaxDynamicSharedMemorySize,
                         K1_SMEM_FLOATS * 4);
    cudaFuncSetAttribute(k_node_out, cudaFuncAttributeMaxDynamicSharedMemorySize,
                         K2_SMEM_FLOATS * 4);

    void* cnt_ptr = nullptr;
    cudaGetSymbolAddress(&cnt_ptr, g_cnt);
    cudaMemsetAsync(cnt_ptr, 0, sizeof(int) * N_NODES, 0);

    // k_edge_mlp stays in the profiled (5th) slot:
    // memset(1), hist(2), scan(3), scatter(4), edge_mlp(5), node_up, prep, gather, node_out
    k_hist<<<N_EDGES / 256, 256>>>(dst);
    k_scan<<<1, 1024>>>();
    k_scatter<<<N_EDGES / 256, 256>>>(dst);
    k_edge_mlp<<<148, 512, K1_SMEM_FLOATS * 4>>>(ef, Wr1, Wr2, Wr3, Wr4);
    k_node_up<<<N_NODES / 8, 256>>>(nf, Wu0, Wu1);
    k_prep<<<160, 256>>>(Ws0, Ws1);
    k_gather<<<N_NODES / 4, 256>>>(ea, src);
    k_node_out<<<N_NODES / NOB, 256, K2_SMEM_FLOATS * 4>>>(na, Wl0, Wl1, out);
}

// round 17
// speedup vs baseline: 1.9718x; 1.2455x over previous
#include <cuda_runtime.h>
#include <cuda_fp16.h>
#include <cstdint>
#include <cstddef>

#define N_NODES 32768
#define N_EDGES 524288

// ---- scratch (device globals; allocations forbidden) ----
__device__ float  g_x[(size_t)N_NODES * 256];     // [0:64]=x0, [64+u*3+i]=x1[u][i]
__device__ float  g_m[(size_t)N_NODES * 512];     // [0:128]=m0, [128+v*3+i]=m1
__device__ __half g_tpw[(size_t)N_EDGES * 256];   // per-edge radial MLP output (fp16)
__device__ float  g_wt0[64 * 640];                // W_skip0 as [v][w][u]
__device__ float  g_wt1[64 * 640];
__device__ int    g_cnt[N_NODES];
__device__ int    g_cur[N_NODES];
__device__ int    g_rowptr[N_NODES + 1];
__device__ int    g_eid[N_EDGES];

#define C_UP      0.125f
#define C_R1      0.35355339059327373f
#define C_R       0.125f
#define C_LIN     0.00552427172801990f
#define C_SKIP    0.03952847075210474f
#define INV_SQRT3 0.5773502691896258f

__device__ __forceinline__ float silu_f(float x) {
    return __fdividef(x, 1.0f + __expf(-x));
}

// ==== K_prep: W_skip (64,64,10)[u,v,w] -> [v][w][u] ====
__global__ void k_prep(const float* __restrict__ Ws0, const float* __restrict__ Ws1) {
    int idx = blockIdx.x * 256 + threadIdx.x;   // 0..40959
    int v = idx / 640, r = idx % 640;
    int w = r / 64, u = r % 64;
    g_wt0[idx] = Ws0[u * 640 + v * 10 + w];
    g_wt1[idx] = Ws1[u * 640 + v * 10 + w];
}

// ==== K0: node up-projection (8 nodes/block) ====
__global__ __launch_bounds__(256) void k_node_up(const float* __restrict__ nf,
                                                 const float* __restrict__ Wu0,
                                                 const float* __restrict__ Wu1) {
    __shared__ float sW0[4096], sW1[4096], sIn[2048];
    const int t = threadIdx.x;
    for (int i = t; i < 4096; i += 256) { sW0[i] = Wu0[i]; sW1[i] = Wu1[i]; }
    const int n0 = blockIdx.x * 8;
    for (int i = t; i < 2048; i += 256) sIn[i] = nf[(size_t)n0 * 256 + i];
    __syncthreads();
    const int j = t >> 6, u = t & 63;
    const int off0 = (j == 0) ? 0 : (63 + j);
    const int st = (j == 0) ? 1 : 3;
    const float* W = (j == 0) ? sW0 : sW1;
    const int oo = (j == 0) ? u : (64 + u * 3 + (j - 1));
    for (int c = 0; c < 2; c++) {
        float acc[4] = {0.f, 0.f, 0.f, 0.f};
        #pragma unroll 8
        for (int v = 0; v < 64; v++) {
            float w = W[v * 64 + u];
            #pragma unroll
            for (int r = 0; r < 4; r++)
                acc[r] += sIn[(c * 4 + r) * 256 + off0 + v * st] * w;
        }
        #pragma unroll
        for (int r = 0; r < 4; r++)
            g_x[(size_t)(n0 + c * 4 + r) * 256 + oo] = acc[r] * C_UP;
    }
}

// ==== CSR build over dst ====
__global__ void k_hist(const int* __restrict__ dst) {
    int e = blockIdx.x * 256 + threadIdx.x;
    atomicAdd(&g_cnt[dst[e]], 1);
}

__global__ __launch_bounds__(1024) void k_scan() {
    __shared__ int part[1024];
    const int t = threadIdx.x;
    int4 c4[8];
    const int4* cp = (const int4*)(g_cnt + t * 32);
    #pragma unroll
    for (int j = 0; j < 8; j++) c4[j] = cp[j];
    int vals[32];
    #pragma unroll
    for (int j = 0; j < 8; j++) {
        vals[j*4+0] = c4[j].x; vals[j*4+1] = c4[j].y;
        vals[j*4+2] = c4[j].z; vals[j*4+3] = c4[j].w;
    }
    int loc[32];
    int s = 0;
    #pragma unroll
    for (int j = 0; j < 32; j++) { loc[j] = s; s += vals[j]; }
    part[t] = s;
    __syncthreads();
    for (int off = 1; off < 1024; off <<= 1) {
        int v = (t >= off) ? part[t - off] : 0;
        __syncthreads();
        part[t] += v;
        __syncthreads();
    }
    int pre = (t == 0) ? 0 : part[t - 1];
    #pragma unroll
    for (int j = 0; j < 32; j++) {
        int o = pre + loc[j];
        g_rowptr[t * 32 + j] = o;
        g_cur[t * 32 + j] = o;
    }
    if (t == 1023) g_rowptr[N_NODES] = part[1023];
}

__global__ void k_scatter(const int* __restrict__ dst) {
    int e = blockIdx.x * 256 + threadIdx.x;
    int p = atomicAdd(&g_cur[dst[e]], 1);
    g_eid[p] = e;
}

// ==== K1: radial MLP -> g_tpw (fp16). L1-3 fp32 scalar, L4 via HMMA ====
#define ST_H  68
#define ST_HH 72                           // fp16 h stride (halves)
#define ST_WT 72                           // fp16 W4^T stride (halves)
#define OFF_WR1  0
#define OFF_WR2  512
#define OFF_WR3  4608
#define OFF_WR4T 8704                      // 256*72 halves = 9216 floats
#define OFF_HA   17920
#define OFF_HB   (OFF_HA + 128*ST_H)       // 26624
#define OFF_HH   (OFF_HB + 128*ST_H)       // 35328 ; 128*72 halves = 4608 floats
#define OFF_EF   (OFF_HH + 4608)           // 39936
#define K1_SMEM_FLOATS (OFF_EF + 1024)     // 40960 floats -> 163840 B

// Layers 1-2 (and 3 via HOUT): thread owns cols {c4..c4+3} and {32+c4..+3}.
// All B LDS.128 conflict-free; fp32 STS.128 conflict-free (ST_H=68).
template<int K, bool SILU>
__device__ __forceinline__ void gemm_t(const float* __restrict__ A, int astride,
                                       const float* __restrict__ B,
                                       float* __restrict__ O,
                                       float scale, int e0, int e1, int c4) {
    float acc[2][8];
    #pragma unroll
    for (int r = 0; r < 2; r++)
        #pragma unroll
        for (int j = 0; j < 8; j++) acc[r][j] = 0.f;
    #pragma unroll 8
    for (int k = 0; k < K; k++) {
        float a0 = A[e0 * astride + k];
        float a1 = A[e1 * astride + k];
        const float4 bl = *(const float4*)(B + k * 64 + c4);
        const float4 bh = *(const float4*)(B + k * 64 + 32 + c4);
        acc[0][0] += a0*bl.x; acc[0][1] += a0*bl.y; acc[0][2] += a0*bl.z; acc[0][3] += a0*bl.w;
        acc[0][4] += a0*bh.x; acc[0][5] += a0*bh.y; acc[0][6] += a0*bh.z; acc[0][7] += a0*bh.w;
        acc[1][0] += a1*bl.x; acc[1][1] += a1*bl.y; acc[1][2] += a1*bl.z; acc[1][3] += a1*bl.w;
        acc[1][4] += a1*bh.x; acc[1][5] += a1*bh.y; acc[1][6] += a1*bh.z; acc[1][7] += a1*bh.w;
    }
    #pragma unroll
    for (int r = 0; r < 2; r++) {
        const int e = r ? e1 : e0;
        float v[8];
        #pragma unroll
        for (int j = 0; j < 8; j++) {
            float x = acc[r][j] * scale;
            v[j] = SILU ? silu_f(x) : x;
        }
        *(float4*)(O + e * ST_H + c4)      = make_float4(v[0], v[1], v[2], v[3]);
        *(float4*)(O + e * ST_H + 32 + c4) = make_float4(v[4], v[5], v[6], v[7]);
    }
}

// Layer 3: same as gemm_t but silu output converted to fp16 into Hh [e][72].
__device__ __forceinline__ void gemm_t_h(const float* __restrict__ A,
                                         const float* __restrict__ B,
                                         __half* __restrict__ Hh,
                                         int e0, int e1, int c4) {
    float acc[2][8];
    #pragma unroll
    for (int r = 0; r < 2; r++)
        #pragma unroll
        for (int j = 0; j < 8; j++) acc[r][j] = 0.f;
    #pragma unroll 8
    for (int k = 0; k < 64; k++) {
        float a0 = A[e0 * ST_H + k];
        float a1 = A[e1 * ST_H + k];
        const float4 bl = *(const float4*)(B + k * 64 + c4);
        const float4 bh = *(const float4*)(B + k * 64 + 32 + c4);
        acc[0][0] += a0*bl.x; acc[0][1] += a0*bl.y; acc[0][2] += a0*bl.z; acc[0][3] += a0*bl.w;
        acc[0][4] += a0*bh.x; acc[0][5] += a0*bh.y; acc[0][6] += a0*bh.z; acc[0][7] += a0*bh.w;
        acc[1][0] += a1*bl.x; acc[1][1] += a1*bl.y; acc[1][2] += a1*bl.z; acc[1][3] += a1*bl.w;
        acc[1][4] += a1*bh.x; acc[1][5] += a1*bh.y; acc[1][6] += a1*bh.z; acc[1][7] += a1*bh.w;
    }
    #pragma unroll
    for (int r = 0; r < 2; r++) {
        const int e = r ? e1 : e0;
        float v[8];
        #pragma unroll
        for (int j = 0; j < 8; j++) v[j] = silu_f(acc[r][j] * C_R);
        __half* hb = Hh + e * ST_HH;
        *(__half2*)(hb + c4)          = __floats2half2_rn(v[0], v[1]);
        *(__half2*)(hb + c4 + 2)      = __floats2half2_rn(v[2], v[3]);
        *(__half2*)(hb + 32 + c4)     = __floats2half2_rn(v[4], v[5]);
        *(__half2*)(hb + 32 + c4 + 2) = __floats2half2_rn(v[6], v[7]);
    }
}

// L4 via mma.sync.m16n8k16 (fp16 in, fp32 acc). Warp w: row-block rb=w>>1
// (16 edges), col half (w&1)*128. 4 k-steps x 16 col-blocks = 64 HMMA/warp.
__device__ __forceinline__ void l4_mma(const __half* __restrict__ Hh,
                                       const __half* __restrict__ W4t,
                                       __half* __restrict__ gout, int t) {
    const int w = t >> 5, lane = t & 31;
    const int rb = w >> 1;
    const int nhalf = (w & 1) * 128;
    const int grp = lane >> 2, qp = lane & 3;
    const int row0 = rb * 16 + grp, row1 = row0 + 8;
    float acc[16][4];
    #pragma unroll
    for (int cb = 0; cb < 16; cb++)
        acc[cb][0] = acc[cb][1] = acc[cb][2] = acc[cb][3] = 0.f;
    #pragma unroll
    for (int ks = 0; ks < 4; ks++) {
        const int k0 = ks * 16;
        const unsigned a0 = *(const unsigned*)(Hh + row0 * ST_HH + k0 + qp * 2);
        const unsigned a1 = *(const unsigned*)(Hh + row1 * ST_HH + k0 + qp * 2);
        const unsigned a2 = *(const unsigned*)(Hh + row0 * ST_HH + k0 + 8 + qp * 2);
        const unsigned a3 = *(const unsigned*)(Hh + row1 * ST_HH + k0 + 8 + qp * 2);
        #pragma unroll
        for (int cb = 0; cb < 16; cb++) {
            const int nrow = nhalf + cb * 8 + grp;
            const unsigned b0 = *(const unsigned*)(W4t + nrow * ST_WT + k0 + qp * 2);
            const unsigned b1 = *(const unsigned*)(W4t + nrow * ST_WT + k0 + 8 + qp * 2);
            asm volatile(
                "mma.sync.aligned.m16n8k16.row.col.f32.f16.f16.f32 "
                "{%0,%1,%2,%3}, {%4,%5,%6,%7}, {%8,%9}, {%0,%1,%2,%3};"
                : "+f"(acc[cb][0]), "+f"(acc[cb][1]),
                  "+f"(acc[cb][2]), "+f"(acc[cb][3])
                : "r"(a0), "r"(a1), "r"(a2), "r"(a3), "r"(b0), "r"(b1));
        }
    }
    #pragma unroll
    for (int cb = 0; cb < 16; cb++) {
        const int nc = nhalf + cb * 8 + qp * 2;
        __half2 h0 = __floats2half2_rn(acc[cb][0] * C_R, acc[cb][1] * C_R);
        __half2 h1 = __floats2half2_rn(acc[cb][2] * C_R, acc[cb][3] * C_R);
        *(__half2*)(gout + (size_t)row0 * 256 + nc) = h0;
        *(__half2*)(gout + (size_t)row1 * 256 + nc) = h1;
    }
}

__global__ __launch_bounds__(512, 1) void k_edge_mlp(const float* __restrict__ ef,
                                                     const float* __restrict__ Wr1,
                                                     const float* __restrict__ Wr2,
                                                     const float* __restrict__ Wr3,
                                                     const float* __restrict__ Wr4) {
    extern __shared__ float sm[];
    float*  sWr1  = sm + OFF_WR1;
    float*  sWr2  = sm + OFF_WR2;
    float*  sWr3  = sm + OFF_WR3;
    __half* sWr4t = (__half*)(sm + OFF_WR4T);
    float*  sHa   = sm + OFF_HA;
    float*  sHb   = sm + OFF_HB;
    __half* sHh   = (__half*)(sm + OFF_HH);
    float*  sEF   = sm + OFF_EF;
    const int t = threadIdx.x;
    if (t < 512) sWr1[t] = Wr1[t];
    for (int i = t; i < 4096; i += 512) { sWr2[i] = Wr2[i]; sWr3[i] = Wr3[i]; }
    for (int i = t; i < 16384; i += 512) {
        int n = i >> 6, k = i & 63;
        sWr4t[n * ST_WT + k] = __float2half(Wr4[k * 256 + n]);
    }
    const int te = t >> 3, tc = t & 7;
    const int e0 = te * 2, e1 = te * 2 + 1, c4 = tc * 4;

    for (int tile = blockIdx.x; tile < N_EDGES / 128; tile += gridDim.x) {
        const int eg = tile * 128;
        __syncthreads();
        for (int i = t; i < 1024; i += 512) sEF[i] = ef[(size_t)eg * 8 + i];
        __syncthreads();
        gemm_t<8,  true>(sEF, 8,    sWr1, sHa, C_R1, e0, e1, c4);
        __syncthreads();
        gemm_t<64, true>(sHa, ST_H, sWr2, sHb, C_R,  e0, e1, c4);
        __syncthreads();
        gemm_t_h(sHb, sWr3, sHh, e0, e1, c4);
        __syncthreads();
        l4_mma(sHh, sWr4t, g_tpw + (size_t)eg * 256, t);
    }
}

// ==== K_gather: CSR walk per node; ea via LDG.128; eid prefetch ====
__global__ __launch_bounds__(256) void k_gather(const float* __restrict__ ea,
                                                const int* __restrict__ src) {
    const int t = threadIdx.x;
    const int n = blockIdx.x * 4 + (t >> 6);
    const int u = t & 63;
    const int beg = g_rowptr[n], end = g_rowptr[n + 1];
    float m0a = 0.f, m0b = 0.f;
    float m1a0 = 0.f, m1a1 = 0.f, m1a2 = 0.f;
    float m1b0 = 0.f, m1b1 = 0.f, m1b2 = 0.f;
    if (beg < end) {
        int e = __ldg(g_eid + beg);
        for (int idx = beg; idx < end; idx++) {
            const int e_nx = (idx + 1 < end) ? __ldg(g_eid + idx + 1) : 0;
            const float4 av = __ldg((const float4*)(ea + (size_t)e * 4));
            const int sn = __ldg(src + e);
            const float sh0 = av.x, a1 = av.y, a2 = av.z, a3 = av.w;
            const float* xr = g_x + (size_t)sn * 256;
            const float s  = xr[u];
            const float v0 = xr[64 + u * 3 + 0];
            const float v1 = xr[64 + u * 3 + 1];
            const float v2 = xr[64 + u * 3 + 2];
            const __half* tp = g_tpw + (size_t)e * 256;
            const float t0 = __half2float(tp[u]);
            const float t1 = __half2float(tp[64 + u]);
            const float t2 = __half2float(tp[128 + u]);
            const float t3 = __half2float(tp[192 + u]);
            m0a += t0 * s * sh0;
            const float dv = v0 * a1 + v1 * a2 + v2 * a3;
            m0b += t3 * dv * INV_SQRT3;
            const float ts = t1 * s;
            m1a0 += ts * a1; m1a1 += ts * a2; m1a2 += ts * a3;
            const float tv = t2 * sh0;
            m1b0 += tv * v0; m1b1 += tv * v1; m1b2 += tv * v2;
            e = e_nx;
        }
    }
    float* mr = g_m + (size_t)n * 512;
    mr[u] = m0a;
    mr[64 + u] = m0b;
    mr[128 + u * 3 + 0] = m1a0;
    mr[128 + u * 3 + 1] = m1a1;
    mr[128 + u * 3 + 2] = m1a2;
    mr[320 + u * 3 + 0] = m1b0;
    mr[320 + u * 3 + 1] = m1b1;
    mr[320 + u * 3 + 2] = m1b2;
}

// ==== K2: node output, 16 nodes/block; phase-B uses [v][w][u] broadcast ====
#define NOB 16
#define O2_WL0 0
#define O2_WL1 8192
#define O2_M   16384
#define O2_Y   24576
#define O2_A   28672
#define K2_SMEM_FLOATS (O2_A + 192)

__global__ __launch_bounds__(256, 2) void k_node_out(const float* __restrict__ na,
                                                     const float* __restrict__ Wl0,
                                                     const float* __restrict__ Wl1,
                                                     float* __restrict__ out) {
    extern __shared__ float sm[];
    float* sWl0 = sm + O2_WL0;
    float* sWl1 = sm + O2_WL1;
    float* sWt  = sm;
    float* sM   = sm + O2_M;
    float* sY   = sm + O2_Y;
    float* sA   = sm + O2_A;
    const int t = threadIdx.x;
    const int n0 = blockIdx.x * NOB;
    for (int i = t; i < 8192; i += 256) { sWl0[i] = Wl0[i]; sWl1[i] = Wl1[i]; }
    for (int i = t; i < NOB * 512; i += 256) sM[i] = g_m[(size_t)n0 * 512 + i];
    for (int i = t; i < NOB * 12; i += 256) {
        int n = i / 12, w = i % 12;
        sA[i] = (w < 10) ? na[(size_t)(n0 + n) * 10 + w] : 0.f;
    }
    __syncthreads();
    const int n4 = t >> 6, u = t & 63;

    float y[16];
    #pragma unroll
    for (int i = 0; i < 16; i++) y[i] = 0.f;
    #pragma unroll 4
    for (int v = 0; v < 128; v++) {
        float w0 = sWl0[v * 64 + u], w1 = sWl1[v * 64 + u];
        #pragma unroll
        for (int ns = 0; ns < 4; ns++) {
            const float* m = sM + (ns * 4 + n4) * 512;
            y[ns*4+0] += m[v] * w0;
            y[ns*4+1] += m[128 + v*3 + 0] * w1;
            y[ns*4+2] += m[128 + v*3 + 1] * w1;
            y[ns*4+3] += m[128 + v*3 + 2] * w1;
        }
    }
    #pragma unroll
    for (int ns = 0; ns < 4; ns++) {
        float* yb = sY + (ns * 4 + n4) * 256;
        yb[u]       = y[ns*4+0] * C_LIN;
        yb[64 + u]  = y[ns*4+1] * C_LIN;
        yb[128 + u] = y[ns*4+2] * C_LIN;
        yb[192 + u] = y[ns*4+3] * C_LIN;
    }
    float areg[40];
    #pragma unroll
    for (int ns = 0; ns < 4; ns++)
        #pragma unroll
        for (int w = 0; w < 10; w++)
            areg[ns*10 + w] = sA[(ns*4 + n4) * 12 + w];

    float z[16];
    #pragma unroll
    for (int i = 0; i < 16; i++) z[i] = 0.f;
    for (int vc = 0; vc < 8; vc++) {
        __syncthreads();
        const int v0 = vc * 8;
        const float4* g0p = (const float4*)(g_wt0 + (size_t)v0 * 640);
        const float4* g1p = (const float4*)(g_wt1 + (size_t)v0 * 640);
        float4* d0 = (float4*)sWt;
        float4* d1 = (float4*)(sWt + 5120);
        for (int i = t; i < 1280; i += 256) { d0[i] = g0p[i]; d1[i] = g1p[i]; }
        __syncthreads();
        #pragma unroll
        for (int v = 0; v < 8; v++) {
            const float* w0b = sWt + v * 640 + u;
            const float* w1b = sWt + 5120 + v * 640 + u;
            float g0[4] = {0.f, 0.f, 0.f, 0.f}, g1[4] = {0.f, 0.f, 0.f, 0.f};
            #pragma unroll
            for (int w = 0; w < 10; w++) {
                float lw0 = w0b[w * 64];
                float lw1 = w1b[w * 64];
                #pragma unroll
                for (int ns = 0; ns < 4; ns++) {
                    g0[ns] += areg[ns*10 + w] * lw0;
                    g1[ns] += areg[ns*10 + w] * lw1;
                }
            }
            #pragma unroll
            for (int ns = 0; ns < 4; ns++) {
                const float* yp = sY + (ns * 4 + n4) * 256 + v0 + v;
                z[ns*4+0] += yp[0]   * g0[ns];
                z[ns*4+1] += yp[64]  * g1[ns];
                z[ns*4+2] += yp[128] * g1[ns];
                z[ns*4+3] += yp[192] * g1[ns];
            }
        }
    }
    #pragma unroll
    for (int ns = 0; ns < 4; ns++) {
        float* o = out + (size_t)(n0 + ns * 4 + n4) * 256;
        o[u]            = z[ns*4+0] * C_SKIP;
        o[64 + u*3 + 0] = z[ns*4+1] * C_SKIP;
        o[64 + u*3 + 1] = z[ns*4+2] * C_SKIP;
        o[64 + u*3 + 2] = z[ns*4+3] * C_SKIP;
    }
}

extern "C" void kernel_launch(void* const* d_in, const int* in_sizes, int n_in,
                              void* d_out, int out_size) {
    const float* nf  = (const float*)d_in[0];
    const float* na  = (const float*)d_in[1];
    const float* ef  = (const float*)d_in[2];
    const float* ea  = (const float*)d_in[3];
    const int*   src = (const int*)d_in[4];
    const int*   dst = (const int*)d_in[5];
    const float* Wu0 = (const float*)d_in[6];
    const float* Wu1 = (const float*)d_in[7];
    const float* Wr1 = (const float*)d_in[8];
    const float* Wr2 = (const float*)d_in[9];
    const float* Wr3 = (const float*)d_in[10];
    const float* Wr4 = (const float*)d_in[11];
    const float* Wl0 = (const float*)d_in[12];
    const float* Wl1 = (const float*)d_in[13];
    const float* Ws0 = (const float*)d_in[14];
    const float* Ws1 = (const float*)d_in[15];
    float* out = (float*)d_out;

    cudaFuncSetAttribute(k_edge_mlp, cudaFuncAttributeMaxDynamicSharedMemorySize,
                         K1_SMEM_FLOATS * 4);
    cudaFuncSetAttribute(k_node_out, cudaFuncAttributeMaxDynamicSharedMemorySize,
                         K2_SMEM_FLOATS * 4);

    void* cnt_ptr = nullptr;
    cudaGetSymbolAddress(&cnt_ptr, g_cnt);
    cudaMemsetAsync(cnt_ptr, 0, sizeof(int) * N_NODES, 0);

    // k_edge_mlp stays in the profiled (5th) slot:
    k_hist<<<N_EDGES / 256, 256>>>(dst);
    k_scan<<<1, 1024>>>();
    k_scatter<<<N_EDGES / 256, 256>>>(dst);
    k_edge_mlp<<<148, 512, K1_SMEM_FLOATS * 4>>>(ef, Wr1, Wr2, Wr3, Wr4);
    k_node_up<<<N_NODES / 8, 256>>>(nf, Wu0, Wu1);
    k_prep<<<160, 256>>>(Ws0, Ws1);
    k_gather<<<N_NODES / 4, 256>>>(ea, src);
    k_node_out<<<N_NODES / NOB, 256, K2_SMEM_FLOATS * 4>>>(na, Wl0, Wl1, out);
}